// round 13
// baseline (speedup 1.0000x reference)
#include <cuda_runtime.h>
#include <cuda_bf16.h>
#include <cuda_fp16.h>
#include <math.h>
#include <stdint.h>

#define B    2
#define CIN  320
#define CENC 326
#define L    4096

#define CENC_P 352   // padded to multiple of 32
#define CIN_P  320

#define STRD 72      // bf16 row stride, K/Q attention tiles (144B)
#define VSTR 136     // fp16 row stride, V attention tiles (272B; 128-j rows)
#define WST2 40      // bf16 row stride in proj smem tiles (80B rows, 32-c chunks)

#define SPLIT 4
#define JSPAN (L / SPLIT)    // 1024
#define NJ    128
#define NTILE (JSPAN / NJ)   // 8
#define MQ    128            // queries per CTA (32 rows per warp, 2 m-groups)
#define NIT   (L / MQ)       // 32 i-tiles

#define LOG2E 1.4426950408889634f

// ---------------- scratch (device globals) ----------------
__device__ __nv_bfloat16 g_Qhi[B * L * 64];          // pre-scaled by log2e
__device__ __nv_bfloat16 g_Khi[B * L * 64];
__device__ __half        g_Vt[B * 64 * L];           // [b][v][l] fp16
__device__ __nv_bfloat16 g_Whq[64 * CENC_P], g_Wlq[64 * CENC_P];   // [d][c] hi/lo
__device__ __nv_bfloat16 g_Whk[64 * CENC_P], g_Wlk[64 * CENC_P];
__device__ __nv_bfloat16 g_Whv[64 * CIN_P],  g_Wlv[64 * CIN_P];
__device__ __half g_pO[SPLIT][B * 64 * L];   // partial O (fp16), [sp][b][v][i]
__device__ float  g_pd[SPLIT][B * L];        // partial denominators
__device__ unsigned g_ctr[B * NIT];          // split-completion counters (zero-init)

// ---------------- helpers ----------------
__device__ __forceinline__ uint32_t smem_u32(const void* p) {
    uint32_t a;
    asm("{ .reg .u64 t; cvta.to.shared.u64 t, %1; cvt.u32.u64 %0, t; }" : "=r"(a) : "l"(p));
    return a;
}
__device__ __forceinline__ void ldsm4(uint32_t r[4], uint32_t addr) {
    asm volatile("ldmatrix.sync.aligned.m8n8.x4.shared.b16 {%0,%1,%2,%3}, [%4];"
        : "=r"(r[0]), "=r"(r[1]), "=r"(r[2]), "=r"(r[3]) : "r"(addr));
}
__device__ __forceinline__ void mma_bf16(float c[4], const uint32_t a[4],
                                         uint32_t b0, uint32_t b1) {
    asm volatile("mma.sync.aligned.m16n8k16.row.col.f32.bf16.bf16.f32 "
        "{%0,%1,%2,%3}, {%4,%5,%6,%7}, {%8,%9}, {%0,%1,%2,%3};"
        : "+f"(c[0]), "+f"(c[1]), "+f"(c[2]), "+f"(c[3])
        : "r"(a[0]), "r"(a[1]), "r"(a[2]), "r"(a[3]), "r"(b0), "r"(b1));
}
__device__ __forceinline__ void mma_fp16(float c[4], const uint32_t a[4],
                                         uint32_t b0, uint32_t b1) {
    asm volatile("mma.sync.aligned.m16n8k16.row.col.f32.f16.f16.f32 "
        "{%0,%1,%2,%3}, {%4,%5,%6,%7}, {%8,%9}, {%0,%1,%2,%3};"
        : "+f"(c[0]), "+f"(c[1]), "+f"(c[2]), "+f"(c[3])
        : "r"(a[0]), "r"(a[1]), "r"(a[2]), "r"(a[3]), "r"(b0), "r"(b1));
}
__device__ __forceinline__ float ex2f(float x) {
    float r;
    asm("ex2.approx.ftz.f32 %0, %1;" : "=f"(r) : "f"(x));
    return r;
}
__device__ __forceinline__ void cpa16(uint32_t dst, const void* src) {
    asm volatile("cp.async.cg.shared.global [%0], [%1], 16;" :: "r"(dst), "l"(src));
}
#define CPA_COMMIT() asm volatile("cp.async.commit_group;" ::: "memory")
#define CPA_WAIT1()  asm volatile("cp.async.wait_group 1;" ::: "memory")
#define CPA_WAIT0()  asm volatile("cp.async.wait_group 0;" ::: "memory")

// ---------------- weight prep (single launch): W[d][c] fp32 -> bf16 hi/lo ----------
__global__ void prep_w_kernel(const float* __restrict__ Wq, const float* __restrict__ Wk,
                              const float* __restrict__ Wv) {
    int which = blockIdx.y;
    const float* W = (which == 0) ? Wq : (which == 1) ? Wk : Wv;
    __nv_bfloat16* Wh = (which == 0) ? g_Whq : (which == 1) ? g_Whk : g_Whv;
    __nv_bfloat16* Wl = (which == 0) ? g_Wlq : (which == 1) ? g_Wlk : g_Wlv;
    int Cdim = (which == 2) ? CIN : CENC;
    int Cpad = (which == 2) ? CIN_P : CENC_P;
    int idx = blockIdx.x * blockDim.x + threadIdx.x;
    if (idx < 64 * Cpad) {
        int d = idx / Cpad, c = idx - d * Cpad;
        float v = (c < Cdim) ? W[d * Cdim + c] : 0.f;
        __nv_bfloat16 h = __float2bfloat16(v);
        Wh[idx] = h;
        Wl[idx] = __float2bfloat16(v - __bfloat162float(h));
    }
}

// ---------------- tensor-core projections (KC=32 chunks, W reg-prefetch) ----------
__global__ __launch_bounds__(128) void proj_kernel(const float* __restrict__ x,
                                                   const float* __restrict__ x_enc,
                                                   const float* __restrict__ bq,
                                                   const float* __restrict__ bk,
                                                   const float* __restrict__ bv) {
    int z = blockIdx.z, b = blockIdx.y, l0 = blockIdx.x * 64;
    const float* src  = (z == 2) ? x : x_enc;
    const __nv_bfloat16* Wh = (z == 0) ? g_Whq : (z == 1) ? g_Whk : g_Whv;
    const __nv_bfloat16* Wl = (z == 0) ? g_Wlq : (z == 1) ? g_Wlk : g_Wlv;
    const float* bias = (z == 0) ? bq : (z == 1) ? bk : bv;
    int Cdim = (z == 2) ? CIN : CENC;
    int Cpad = (z == 2) ? CIN_P : CENC_P;

    extern __shared__ char psm[];
    __nv_bfloat16* Xh  = (__nv_bfloat16*)(psm);
    __nv_bfloat16* Xl  = (__nv_bfloat16*)(psm + 5120);
    __nv_bfloat16* Whs = (__nv_bfloat16*)(psm + 10240);
    __nv_bfloat16* Wls = (__nv_bfloat16*)(psm + 15360);
    __shared__ float nrmA[64];
    uint32_t sb = smem_u32(psm);

    int t = threadIdx.x, lane = t & 31, w = t >> 5;
    int gid = lane >> 2, tig = lane & 3, lr = lane & 7, lg = lane >> 3;

    float S[8][4];
#pragma unroll
    for (int n = 0; n < 8; ++n)
#pragma unroll
        for (int q = 0; q < 4; ++q) S[n][q] = 0.f;

    const float* srcb = src + (size_t)b * Cdim * L + l0;
    const uint32_t offB = (uint32_t)(((lr + (lg >> 1) * 8) * WST2 + (lg & 1) * 8) * 2);
    const uint32_t bX = sb + offB;

    int nCh = Cpad / 32;
    int wd = t >> 4, wcp = t & 15;    // W staging coords (d = wd + i*8, c-pair = wcp)

    // prefetch chunk 0 (X into xv, W into uwh/uwl)
    float xv[16];
    uint32_t uwh[8], uwl[8];
#pragma unroll
    for (int i = 0; i < 16; ++i) {
        int idx = t + i * 128;
        int c = idx >> 6, l = idx & 63;
        xv[i] = (c < Cdim) ? __ldg(srcb + (size_t)c * L + l) : 0.f;
    }
#pragma unroll
    for (int i = 0; i < 8; ++i) {
        int d = wd + i * 8;
        uwh[i] = *(const uint32_t*)&Wh[d * Cpad + wcp * 2];
        uwl[i] = *(const uint32_t*)&Wl[d * Cpad + wcp * 2];
    }

    for (int ch = 0; ch < nCh; ++ch) {
        __syncthreads();
        // store converted X chunk + W chunk (pure STS — LDGs were prefetched)
#pragma unroll
        for (int i = 0; i < 16; ++i) {
            int idx = t + i * 128;
            int c = idx >> 6, l = idx & 63;
            __nv_bfloat16 h = __float2bfloat16(xv[i]);
            Xh[l * WST2 + c] = h;
            Xl[l * WST2 + c] = __float2bfloat16(xv[i] - __bfloat162float(h));
        }
#pragma unroll
        for (int i = 0; i < 8; ++i) {
            int d = wd + i * 8;
            *(uint32_t*)&Whs[d * WST2 + wcp * 2] = uwh[i];
            *(uint32_t*)&Wls[d * WST2 + wcp * 2] = uwl[i];
        }
        __syncthreads();

        // prefetch next chunk (hidden under the mma block below)
        if (ch + 1 < nCh) {
            int c1 = (ch + 1) * 32;
#pragma unroll
            for (int i = 0; i < 16; ++i) {
                int idx = t + i * 128;
                int c = c1 + (idx >> 6), l = idx & 63;
                xv[i] = (c < Cdim) ? __ldg(srcb + (size_t)c * L + l) : 0.f;
            }
#pragma unroll
            for (int i = 0; i < 8; ++i) {
                int d = wd + i * 8;
                uwh[i] = *(const uint32_t*)&Wh[d * Cpad + c1 + wcp * 2];
                uwl[i] = *(const uint32_t*)&Wl[d * Cpad + c1 + wcp * 2];
            }
        }

#pragma unroll
        for (int kb = 0; kb < 2; ++kb) {
            uint32_t ah[4], al[4];
            {
                int r0 = (w * 16 + gid) * WST2 + kb * 16;
                int r8 = (w * 16 + gid + 8) * WST2 + kb * 16;
                ah[0] = *(const uint32_t*)&Whs[r0 + tig * 2];
                ah[1] = *(const uint32_t*)&Whs[r8 + tig * 2];
                ah[2] = *(const uint32_t*)&Whs[r0 + tig * 2 + 8];
                ah[3] = *(const uint32_t*)&Whs[r8 + tig * 2 + 8];
                al[0] = *(const uint32_t*)&Wls[r0 + tig * 2];
                al[1] = *(const uint32_t*)&Wls[r8 + tig * 2];
                al[2] = *(const uint32_t*)&Wls[r0 + tig * 2 + 8];
                al[3] = *(const uint32_t*)&Wls[r8 + tig * 2 + 8];
            }
#pragma unroll
            for (int np = 0; np < 4; ++np) {
                uint32_t bh[4], bl[4];
                ldsm4(bh, bX + (uint32_t)(np * 16 * WST2 * 2 + kb * 32));
                mma_bf16(S[np * 2],     ah, bh[0], bh[1]);
                mma_bf16(S[np * 2 + 1], ah, bh[2], bh[3]);
                mma_bf16(S[np * 2],     al, bh[0], bh[1]);
                mma_bf16(S[np * 2 + 1], al, bh[2], bh[3]);
                ldsm4(bl, bX + (uint32_t)(5120 + np * 16 * WST2 * 2 + kb * 32));
                mma_bf16(S[np * 2],     ah, bl[0], bl[1]);
                mma_bf16(S[np * 2 + 1], ah, bl[2], bl[3]);
            }
        }
    }

    float b0v = __ldg(bias + w * 16 + gid);
    float b8v = __ldg(bias + w * 16 + gid + 8);

    float* Osm = (float*)psm;   // [64][68] floats = 17408B (fits in 20480)
    __syncthreads();

    if (z < 2) {
#pragma unroll
        for (int n = 0; n < 8; ++n) {
            int lc = n * 8 + tig * 2, d0 = w * 16 + gid;
            Osm[lc * 68 + d0]           = S[n][0] + b0v;
            Osm[(lc + 1) * 68 + d0]     = S[n][1] + b0v;
            Osm[lc * 68 + d0 + 8]       = S[n][2] + b8v;
            Osm[(lc + 1) * 68 + d0 + 8] = S[n][3] + b8v;
        }
        __syncthreads();
        if (t < 64) {
            float ss = 0.f;
#pragma unroll
            for (int d = 0; d < 64; ++d) { float v = Osm[t * 68 + d]; ss += v * v; }
            nrmA[t] = 1.f / fmaxf(sqrtf(ss), 1e-6f);
        }
        __syncthreads();
        __nv_bfloat16* dh = (z == 0) ? g_Qhi : g_Khi;
        int l = t & 63, dg = t >> 6;
        float sc = nrmA[l];
        if (z == 0) sc *= LOG2E;
        size_t obase = ((size_t)b * L + l0 + l) * 64 + dg * 32;
#pragma unroll
        for (int i = 0; i < 8; ++i) {
            __nv_bfloat16 th[4];
#pragma unroll
            for (int k = 0; k < 4; ++k)
                th[k] = __float2bfloat16(Osm[l * 68 + dg * 32 + i * 4 + k] * sc);
            *(uint2*)&dh[obase + i * 4] = *(uint2*)th;
        }
    } else {
#pragma unroll
        for (int n = 0; n < 8; ++n) {
            int lc = n * 8 + tig * 2, d0 = w * 16 + gid;
            Osm[d0 * 68 + lc]           = S[n][0] + b0v;
            Osm[d0 * 68 + lc + 1]       = S[n][1] + b0v;
            Osm[(d0 + 8) * 68 + lc]     = S[n][2] + b8v;
            Osm[(d0 + 8) * 68 + lc + 1] = S[n][3] + b8v;
        }
        __syncthreads();
        int v = t >> 1, half = t & 1;
        size_t obase = ((size_t)b * 64 + v) * L + l0 + half * 32;
#pragma unroll
        for (int i = 0; i < 8; ++i) {
            __half th[4];
#pragma unroll
            for (int k = 0; k < 4; ++k)
                th[k] = __float2half(Osm[v * 68 + half * 32 + i * 4 + k]);
            *(uint2*)&g_Vt[obase + i * 4] = *(uint2*)th;
        }
    }
}

// ---------------- mma.sync flash attention + fused split-combine ----------------
#define KHO  0u
#define VHO  18432u
#define STAGEB 35840u

__device__ __forceinline__ void load_kv(uint32_t sbase, int b, int j0, int t) {
#pragma unroll
    for (int i = 0; i < 8; ++i) {
        int idx = t + i * 128;
        int r = idx >> 3, c = idx & 7;
        cpa16(sbase + KHO + (uint32_t)(r * 144 + c * 16),
              g_Khi + ((size_t)b * L + j0 + r) * 64 + c * 8);
    }
#pragma unroll
    for (int i = 0; i < 8; ++i) {
        int idx = t + i * 128;
        int v = idx >> 4, c16 = idx & 15;
        cpa16(sbase + VHO + (uint32_t)(v * 272 + c16 * 16),
              g_Vt + ((size_t)b * 64 + v) * L + j0 + c16 * 8);
    }
}

__global__ __launch_bounds__(128, 3) void attn_kernel(float* __restrict__ out) {
    extern __shared__ char sm[];
    const uint32_t sb = smem_u32(sm);
    const int t = threadIdx.x, lane = t & 31, w = t >> 5;
    const int b = blockIdx.y, i0 = blockIdx.x * MQ, sp = blockIdx.z;
    const int jbase = sp * JSPAN;
    const int gid = lane >> 2, tig = lane & 3;
    const int lr = lane & 7, lg = lane >> 3;

    const uint32_t offA  = (uint32_t)(((lr + ((lg & 1) << 3)) * STRD + ((lg >> 1) << 3)) * 2);
    const uint32_t offBK = (uint32_t)(((lr + ((lg >> 1) << 3)) * STRD + ((lg & 1) << 3)) * 2);
    const uint32_t offBV = (uint32_t)(((lr + ((lg >> 1) << 3)) * VSTR + ((lg & 1) << 3)) * 2);

    // ---- stage Q (128 rows) into stage-0 K area, build persistent A fragments
    {
        const uint4* qh = (const uint4*)(g_Qhi + ((size_t)b * L + i0) * 64);
        for (int idx = t; idx < 1024; idx += 128) {
            int r = idx >> 3, c = idx & 7;
            *(uint4*)(sm + (uint32_t)(r * 144 + c * 16)) = qh[idx];
        }
    }
    __syncthreads();
    uint32_t qf[2][4][4];
#pragma unroll
    for (int mg = 0; mg < 2; ++mg) {
        uint32_t base = sb + (uint32_t)((w * 32 + mg * 16) * STRD * 2) + offA;
#pragma unroll
        for (int kb = 0; kb < 4; ++kb) ldsm4(qf[mg][kb], base + kb * 32);
    }
    __syncthreads();

    load_kv(sb, b, jbase, t);
    CPA_COMMIT();

    float O[2][8][4];
#pragma unroll
    for (int mg = 0; mg < 2; ++mg)
#pragma unroll
        for (int n = 0; n < 8; ++n)
#pragma unroll
            for (int q = 0; q < 4; ++q) O[mg][n][q] = 0.f;
    float dsum[2][2] = {{0.f, 0.f}, {0.f, 0.f}};

#pragma unroll 1
    for (int tile = 0; tile < NTILE; ++tile) {
        int cur = tile & 1;
        if (tile < NTILE - 1) {
            load_kv(sb + (uint32_t)(cur ^ 1) * STAGEB, b, jbase + (tile + 1) * NJ, t);
            CPA_COMMIT();
            CPA_WAIT1();
        } else {
            CPA_WAIT0();
        }
        __syncthreads();

        const uint32_t stg = sb + (uint32_t)cur * STAGEB;

#pragma unroll
        for (int jh = 0; jh < 2; ++jh) {
            const uint32_t bBK = stg + KHO + offBK + (uint32_t)(jh * 64 * 144);
            const uint32_t bBV = stg + VHO + offBV + (uint32_t)(jh * 128);

            float S[2][8][4];
#pragma unroll
            for (int mg = 0; mg < 2; ++mg)
#pragma unroll
                for (int n = 0; n < 8; ++n)
#pragma unroll
                    for (int q = 0; q < 4; ++q) S[mg][n][q] = 0.f;

#pragma unroll
            for (int kb = 0; kb < 4; ++kb) {
#pragma unroll
                for (int np = 0; np < 4; ++np) {
                    uint32_t bh[4];
                    ldsm4(bh, bBK + (uint32_t)(np * 16 * STRD * 2) + kb * 32);
                    mma_bf16(S[0][np * 2],     qf[0][kb], bh[0], bh[1]);
                    mma_bf16(S[0][np * 2 + 1], qf[0][kb], bh[2], bh[3]);
                    mma_bf16(S[1][np * 2],     qf[1][kb], bh[0], bh[1]);
                    mma_bf16(S[1][np * 2 + 1], qf[1][kb], bh[2], bh[3]);
                }
            }

            uint32_t phi[2][4][4];
#pragma unroll
            for (int mg = 0; mg < 2; ++mg) {
                float rl = 0.f, rh = 0.f;
#pragma unroll
                for (int n = 0; n < 8; ++n) {
#pragma unroll
                    for (int q = 0; q < 4; ++q) S[mg][n][q] = ex2f(S[mg][n][q]);
                    rl += S[mg][n][0] + S[mg][n][1];
                    rh += S[mg][n][2] + S[mg][n][3];
                }
                dsum[mg][0] += rl; dsum[mg][1] += rh;
#pragma unroll
                for (int jb = 0; jb < 4; ++jb) {
#pragma unroll
                    for (int rp = 0; rp < 4; ++rp) {
                        int n = jb * 2 + (rp >> 1);
                        __half2 h2 = __floats2half2_rn(S[mg][n][(rp & 1) * 2 + 0],
                                                       S[mg][n][(rp & 1) * 2 + 1]);
                        phi[mg][jb][rp] = *(uint32_t*)&h2;
                    }
                }
            }

#pragma unroll
            for (int jb = 0; jb < 4; ++jb) {
#pragma unroll
                for (int vp = 0; vp < 4; ++vp) {
                    uint32_t bh[4];
                    ldsm4(bh, bBV + (uint32_t)(vp * 16 * VSTR * 2) + jb * 32);
                    mma_fp16(O[0][vp * 2],     phi[0][jb], bh[0], bh[1]);
                    mma_fp16(O[0][vp * 2 + 1], phi[0][jb], bh[2], bh[3]);
                    mma_fp16(O[1][vp * 2],     phi[1][jb], bh[0], bh[1]);
                    mma_fp16(O[1][vp * 2 + 1], phi[1][jb], bh[2], bh[3]);
                }
            }
        }
        __syncthreads();
    }

    // row-sum reduce across lanes; store partial denoms
#pragma unroll
    for (int mg = 0; mg < 2; ++mg) {
#pragma unroll
        for (int h = 0; h < 2; ++h) {
            float v = dsum[mg][h];
            v += __shfl_xor_sync(0xffffffffu, v, 1);
            v += __shfl_xor_sync(0xffffffffu, v, 2);
            if (tig == 0)
                g_pd[sp][(size_t)b * L + i0 + w * 32 + mg * 16 + gid + h * 8] = v;
        }
    }

    // ---- write partial O (un-normalized, fp16) in [v][i] layout via smem transpose
    __syncthreads();
    float* Os = (float*)sm;   // [64][132] floats = 33792B
#pragma unroll
    for (int mg = 0; mg < 2; ++mg) {
        int ir = w * 32 + mg * 16 + gid;
#pragma unroll
        for (int n = 0; n < 8; ++n) {
            int v0 = n * 8 + tig * 2;
            Os[v0 * 132 + ir]            = O[mg][n][0];
            Os[(v0 + 1) * 132 + ir]      = O[mg][n][1];
            Os[v0 * 132 + ir + 8]        = O[mg][n][2];
            Os[(v0 + 1) * 132 + ir + 8]  = O[mg][n][3];
        }
    }
    __syncthreads();
    {
        int v = t >> 1, hc = (t & 1) * 64;
        __half* dst = g_pO[sp] + ((size_t)b * 64 + v) * L + i0 + hc;
        const float* srcp = Os + v * 132 + hc;
#pragma unroll
        for (int c = 0; c < 16; ++c) {
            float4 f = *(const float4*)(srcp + c * 4);
            __half2 h0 = __floats2half2_rn(f.x, f.y);
            __half2 h1 = __floats2half2_rn(f.z, f.w);
            uint2 u;
            u.x = *(uint32_t*)&h0;
            u.y = *(uint32_t*)&h1;
            *(uint2*)(dst + c * 4) = u;
        }
    }

    // ---- fused combine: last-arriving split CTA reduces & writes final output
    __syncthreads();
    __shared__ unsigned s_last;
    if (t == 0) {
        __threadfence();
        unsigned old = atomicAdd(&g_ctr[b * NIT + blockIdx.x], 1u);
        s_last = (old == SPLIT - 1) ? 1u : 0u;
    }
    __syncthreads();
    if (s_last) {
        __threadfence();
        float* dinv = (float*)sm;   // reuse: 128 floats
        {
            float ds = 0.f;
#pragma unroll
            for (int s = 0; s < SPLIT; ++s) ds += g_pd[s][(size_t)b * L + i0 + t];
            dinv[t] = 1.f / ds;
        }
        __syncthreads();
        int v = t >> 1, hc = (t & 1) * 64;
        float* dst = out + ((size_t)b * 64 + v) * L + i0 + hc;
#pragma unroll
        for (int c = 0; c < 16; ++c) {
            float acc[4] = {0.f, 0.f, 0.f, 0.f};
#pragma unroll
            for (int s = 0; s < SPLIT; ++s) {
                uint2 u = *(const uint2*)&g_pO[s][((size_t)b * 64 + v) * L + i0 + hc + c * 4];
                float2 p0 = __half22float2(*(__half2*)&u.x);
                float2 p1 = __half22float2(*(__half2*)&u.y);
                acc[0] += p0.x; acc[1] += p0.y; acc[2] += p1.x; acc[3] += p1.y;
            }
            float4 o;
            o.x = acc[0] * dinv[hc + c * 4 + 0];
            o.y = acc[1] * dinv[hc + c * 4 + 1];
            o.z = acc[2] * dinv[hc + c * 4 + 2];
            o.w = acc[3] * dinv[hc + c * 4 + 3];
            *(float4*)(dst + c * 4) = o;
        }
        if (t == 0) g_ctr[b * NIT + blockIdx.x] = 0;   // reset for next graph replay
    }
}

// ---------------- launch ----------------
extern "C" void kernel_launch(void* const* d_in, const int* in_sizes, int n_in,
                              void* d_out, int out_size) {
    const float* x     = (const float*)d_in[0];
    const float* x_enc = (const float*)d_in[1];
    const float* Wq    = (const float*)d_in[2];
    const float* bq    = (const float*)d_in[3];
    const float* Wk    = (const float*)d_in[4];
    const float* bk    = (const float*)d_in[5];
    const float* Wv    = (const float*)d_in[6];
    const float* bv    = (const float*)d_in[7];
    float* out = (float*)d_out;

    prep_w_kernel<<<dim3((64 * CENC_P + 255) / 256, 3), 256>>>(Wq, Wk, Wv);

    proj_kernel<<<dim3(L / 64, B, 3), 128, 20480>>>(x, x_enc, bq, bk, bv);

    static bool attr_set = false;
    if (!attr_set) {
        cudaFuncSetAttribute(attn_kernel, cudaFuncAttributeMaxDynamicSharedMemorySize,
                             2 * STAGEB);
        attr_set = true;
    }
    attn_kernel<<<dim3(NIT, B, SPLIT), 128, 2 * STAGEB>>>(out);
}

// round 14
// speedup vs baseline: 1.1494x; 1.1494x over previous
#include <cuda_runtime.h>
#include <cuda_bf16.h>
#include <cuda_fp16.h>
#include <math.h>
#include <stdint.h>

#define B    2
#define CIN  320
#define CENC 326
#define L    4096

#define CENC_P 352   // padded to multiple of 32
#define CIN_P  320

#define STRD 72      // bf16 row stride, K/Q attention tiles (144B)
#define VSTR 136     // fp16 row stride, V attention tiles (272B; 128-j rows)
#define WST2 40      // bf16 row stride in proj smem tiles (80B rows, 32-c chunks)

#define SPLIT 4
#define JSPAN (L / SPLIT)    // 1024
#define NJ    128
#define NTILE (JSPAN / NJ)   // 8
#define MQ    128            // queries per CTA (32 rows per warp, 2 m-groups)

#define LOG2E 1.4426950408889634f

// ---------------- scratch (device globals) ----------------
__device__ __nv_bfloat16 g_Qhi[B * L * 64];          // pre-scaled by log2e
__device__ __nv_bfloat16 g_Khi[B * L * 64];
__device__ __half        g_Vt[B * 64 * L];           // [b][v][l] fp16
__device__ __half g_pO[SPLIT][B * 64 * L];   // partial O (fp16), [sp][b][v][i]
__device__ float  g_pd[SPLIT][B * L];        // partial denominators

// ---------------- helpers ----------------
__device__ __forceinline__ uint32_t smem_u32(const void* p) {
    uint32_t a;
    asm("{ .reg .u64 t; cvta.to.shared.u64 t, %1; cvt.u32.u64 %0, t; }" : "=r"(a) : "l"(p));
    return a;
}
__device__ __forceinline__ void ldsm4(uint32_t r[4], uint32_t addr) {
    asm volatile("ldmatrix.sync.aligned.m8n8.x4.shared.b16 {%0,%1,%2,%3}, [%4];"
        : "=r"(r[0]), "=r"(r[1]), "=r"(r[2]), "=r"(r[3]) : "r"(addr));
}
__device__ __forceinline__ void mma_bf16(float c[4], const uint32_t a[4],
                                         uint32_t b0, uint32_t b1) {
    asm volatile("mma.sync.aligned.m16n8k16.row.col.f32.bf16.bf16.f32 "
        "{%0,%1,%2,%3}, {%4,%5,%6,%7}, {%8,%9}, {%0,%1,%2,%3};"
        : "+f"(c[0]), "+f"(c[1]), "+f"(c[2]), "+f"(c[3])
        : "r"(a[0]), "r"(a[1]), "r"(a[2]), "r"(a[3]), "r"(b0), "r"(b1));
}
__device__ __forceinline__ void mma_fp16(float c[4], const uint32_t a[4],
                                         uint32_t b0, uint32_t b1) {
    asm volatile("mma.sync.aligned.m16n8k16.row.col.f32.f16.f16.f32 "
        "{%0,%1,%2,%3}, {%4,%5,%6,%7}, {%8,%9}, {%0,%1,%2,%3};"
        : "+f"(c[0]), "+f"(c[1]), "+f"(c[2]), "+f"(c[3])
        : "r"(a[0]), "r"(a[1]), "r"(a[2]), "r"(a[3]), "r"(b0), "r"(b1));
}
__device__ __forceinline__ float ex2f(float x) {
    float r;
    asm("ex2.approx.ftz.f32 %0, %1;" : "=f"(r) : "f"(x));
    return r;
}
__device__ __forceinline__ void cpa16(uint32_t dst, const void* src) {
    asm volatile("cp.async.cg.shared.global [%0], [%1], 16;" :: "r"(dst), "l"(src));
}
#define CPA_COMMIT() asm volatile("cp.async.commit_group;" ::: "memory")
#define CPA_WAIT1()  asm volatile("cp.async.wait_group 1;" ::: "memory")
#define CPA_WAIT0()  asm volatile("cp.async.wait_group 0;" ::: "memory")

// ---------------- tensor-core projections (KC=32 chunks, inline W hi/lo split) ----
// smem bf16 tiles [64][WST2]=5120B: Xh@0, Xl@5120, Whs@10240, Wls@15360
__global__ __launch_bounds__(128) void proj_kernel(const float* __restrict__ x,
                                                   const float* __restrict__ x_enc,
                                                   const float* __restrict__ Wq,
                                                   const float* __restrict__ Wk,
                                                   const float* __restrict__ Wv,
                                                   const float* __restrict__ bq,
                                                   const float* __restrict__ bk,
                                                   const float* __restrict__ bv) {
    int z = blockIdx.z, b = blockIdx.y, l0 = blockIdx.x * 64;
    const float* src  = (z == 2) ? x : x_enc;
    const float* Wsrc = (z == 0) ? Wq : (z == 1) ? Wk : Wv;
    const float* bias = (z == 0) ? bq : (z == 1) ? bk : bv;
    int Cdim = (z == 2) ? CIN : CENC;
    int Cpad = (z == 2) ? CIN_P : CENC_P;

    extern __shared__ char psm[];
    __nv_bfloat16* Xh  = (__nv_bfloat16*)(psm);
    __nv_bfloat16* Xl  = (__nv_bfloat16*)(psm + 5120);
    __nv_bfloat16* Whs = (__nv_bfloat16*)(psm + 10240);
    __nv_bfloat16* Wls = (__nv_bfloat16*)(psm + 15360);
    __shared__ float nrmA[64];
    uint32_t sb = smem_u32(psm);

    int t = threadIdx.x, lane = t & 31, w = t >> 5;
    int gid = lane >> 2, tig = lane & 3, lr = lane & 7, lg = lane >> 3;

    float S[8][4];
#pragma unroll
    for (int n = 0; n < 8; ++n)
#pragma unroll
        for (int q = 0; q < 4; ++q) S[n][q] = 0.f;

    const float* srcb = src + (size_t)b * Cdim * L + l0;
    const uint32_t offB = (uint32_t)(((lr + (lg >> 1) * 8) * WST2 + (lg & 1) * 8) * 2);
    const uint32_t bX = sb + offB;

    int nCh = Cpad / 32;

    // prefetch chunk 0 (32 channels x 64 positions)
    float xv[16];
#pragma unroll
    for (int i = 0; i < 16; ++i) {
        int idx = t + i * 128;
        int c = idx >> 6, l = idx & 63;
        xv[i] = (c < Cdim) ? __ldg(srcb + (size_t)c * L + l) : 0.f;
    }

    for (int ch = 0; ch < nCh; ++ch) {
        int c0 = ch * 32;
        __syncthreads();
        // store converted X chunk
#pragma unroll
        for (int i = 0; i < 16; ++i) {
            int idx = t + i * 128;
            int c = idx >> 6, l = idx & 63;
            __nv_bfloat16 h = __float2bfloat16(xv[i]);
            Xh[l * WST2 + c] = h;
            Xl[l * WST2 + c] = __float2bfloat16(xv[i] - __bfloat162float(h));
        }
        // stage W tile [64 d][32 c]: read fp32, split to bf16 hi/lo inline
#pragma unroll
        for (int i = 0; i < 8; ++i) {
            int idx = t + i * 128;
            int d = idx >> 4, cp = idx & 15;
            int c = c0 + cp * 2;
            float f0 = (c < Cdim)     ? __ldg(Wsrc + d * Cdim + c)     : 0.f;
            float f1 = (c + 1 < Cdim) ? __ldg(Wsrc + d * Cdim + c + 1) : 0.f;
            __nv_bfloat16 h0 = __float2bfloat16(f0);
            __nv_bfloat16 h1 = __float2bfloat16(f1);
            Whs[d * WST2 + cp * 2]     = h0;
            Whs[d * WST2 + cp * 2 + 1] = h1;
            Wls[d * WST2 + cp * 2]     = __float2bfloat16(f0 - __bfloat162float(h0));
            Wls[d * WST2 + cp * 2 + 1] = __float2bfloat16(f1 - __bfloat162float(h1));
        }
        __syncthreads();

        // prefetch next X chunk
        if (ch + 1 < nCh) {
            int c1 = (ch + 1) * 32;
#pragma unroll
            for (int i = 0; i < 16; ++i) {
                int idx = t + i * 128;
                int c = c1 + (idx >> 6), l = idx & 63;
                xv[i] = (c < Cdim) ? __ldg(srcb + (size_t)c * L + l) : 0.f;
            }
        }

#pragma unroll
        for (int kb = 0; kb < 2; ++kb) {
            uint32_t ah[4], al[4];
            {
                int r0 = (w * 16 + gid) * WST2 + kb * 16;
                int r8 = (w * 16 + gid + 8) * WST2 + kb * 16;
                ah[0] = *(const uint32_t*)&Whs[r0 + tig * 2];
                ah[1] = *(const uint32_t*)&Whs[r8 + tig * 2];
                ah[2] = *(const uint32_t*)&Whs[r0 + tig * 2 + 8];
                ah[3] = *(const uint32_t*)&Whs[r8 + tig * 2 + 8];
                al[0] = *(const uint32_t*)&Wls[r0 + tig * 2];
                al[1] = *(const uint32_t*)&Wls[r8 + tig * 2];
                al[2] = *(const uint32_t*)&Wls[r0 + tig * 2 + 8];
                al[3] = *(const uint32_t*)&Wls[r8 + tig * 2 + 8];
            }
#pragma unroll
            for (int np = 0; np < 4; ++np) {
                uint32_t bh[4], bl[4];
                ldsm4(bh, bX + (uint32_t)(np * 16 * WST2 * 2 + kb * 32));
                mma_bf16(S[np * 2],     ah, bh[0], bh[1]);
                mma_bf16(S[np * 2 + 1], ah, bh[2], bh[3]);
                mma_bf16(S[np * 2],     al, bh[0], bh[1]);
                mma_bf16(S[np * 2 + 1], al, bh[2], bh[3]);
                ldsm4(bl, bX + (uint32_t)(5120 + np * 16 * WST2 * 2 + kb * 32));
                mma_bf16(S[np * 2],     ah, bl[0], bl[1]);
                mma_bf16(S[np * 2 + 1], ah, bl[2], bl[3]);
            }
        }
    }

    float b0v = __ldg(bias + w * 16 + gid);
    float b8v = __ldg(bias + w * 16 + gid + 8);

    float* Osm = (float*)psm;   // [64][68] floats = 17408B (fits in 20480)
    __syncthreads();

    if (z < 2) {
#pragma unroll
        for (int n = 0; n < 8; ++n) {
            int lc = n * 8 + tig * 2, d0 = w * 16 + gid;
            Osm[lc * 68 + d0]           = S[n][0] + b0v;
            Osm[(lc + 1) * 68 + d0]     = S[n][1] + b0v;
            Osm[lc * 68 + d0 + 8]       = S[n][2] + b8v;
            Osm[(lc + 1) * 68 + d0 + 8] = S[n][3] + b8v;
        }
        __syncthreads();
        if (t < 64) {
            float ss = 0.f;
#pragma unroll
            for (int d = 0; d < 64; ++d) { float v = Osm[t * 68 + d]; ss += v * v; }
            nrmA[t] = 1.f / fmaxf(sqrtf(ss), 1e-6f);
        }
        __syncthreads();
        __nv_bfloat16* dh = (z == 0) ? g_Qhi : g_Khi;
        int l = t & 63, dg = t >> 6;
        float sc = nrmA[l];
        if (z == 0) sc *= LOG2E;                 // fold log2e into Q -> ex2 in attn
        size_t obase = ((size_t)b * L + l0 + l) * 64 + dg * 32;
#pragma unroll
        for (int i = 0; i < 8; ++i) {
            __nv_bfloat16 th[4];
#pragma unroll
            for (int k = 0; k < 4; ++k)
                th[k] = __float2bfloat16(Osm[l * 68 + dg * 32 + i * 4 + k] * sc);
            *(uint2*)&dh[obase + i * 4] = *(uint2*)th;
        }
    } else {
#pragma unroll
        for (int n = 0; n < 8; ++n) {
            int lc = n * 8 + tig * 2, d0 = w * 16 + gid;
            Osm[d0 * 68 + lc]           = S[n][0] + b0v;
            Osm[d0 * 68 + lc + 1]       = S[n][1] + b0v;
            Osm[(d0 + 8) * 68 + lc]     = S[n][2] + b8v;
            Osm[(d0 + 8) * 68 + lc + 1] = S[n][3] + b8v;
        }
        __syncthreads();
        int v = t >> 1, half = t & 1;
        size_t obase = ((size_t)b * 64 + v) * L + l0 + half * 32;
#pragma unroll
        for (int i = 0; i < 8; ++i) {
            __half th[4];
#pragma unroll
            for (int k = 0; k < 4; ++k)
                th[k] = __float2half(Osm[v * 68 + half * 32 + i * 4 + k]);
            *(uint2*)&g_Vt[obase + i * 4] = *(uint2*)th;
        }
    }
}

// ---------------- mma.sync flash attention (MQ=128, NJ=128, SPLIT=4, fp16 PV) -----
#define KHO  0u
#define VHO  18432u
#define STAGEB 35840u

__device__ __forceinline__ void load_kv(uint32_t sbase, int b, int j0, int t) {
#pragma unroll
    for (int i = 0; i < 8; ++i) {
        int idx = t + i * 128;
        int r = idx >> 3, c = idx & 7;
        cpa16(sbase + KHO + (uint32_t)(r * 144 + c * 16),
              g_Khi + ((size_t)b * L + j0 + r) * 64 + c * 8);
    }
#pragma unroll
    for (int i = 0; i < 8; ++i) {
        int idx = t + i * 128;
        int v = idx >> 4, c16 = idx & 15;
        cpa16(sbase + VHO + (uint32_t)(v * 272 + c16 * 16),
              g_Vt + ((size_t)b * 64 + v) * L + j0 + c16 * 8);
    }
}

__global__ __launch_bounds__(128, 3) void attn_kernel() {
    extern __shared__ char sm[];
    const uint32_t sb = smem_u32(sm);
    const int t = threadIdx.x, lane = t & 31, w = t >> 5;
    const int b = blockIdx.y, i0 = blockIdx.x * MQ, sp = blockIdx.z;
    const int jbase = sp * JSPAN;
    const int gid = lane >> 2, tig = lane & 3;
    const int lr = lane & 7, lg = lane >> 3;

    const uint32_t offA  = (uint32_t)(((lr + ((lg & 1) << 3)) * STRD + ((lg >> 1) << 3)) * 2);
    const uint32_t offBK = (uint32_t)(((lr + ((lg >> 1) << 3)) * STRD + ((lg & 1) << 3)) * 2);
    const uint32_t offBV = (uint32_t)(((lr + ((lg >> 1) << 3)) * VSTR + ((lg & 1) << 3)) * 2);

    // ---- stage Q (128 rows) into stage-0 K area, build persistent A fragments
    {
        const uint4* qh = (const uint4*)(g_Qhi + ((size_t)b * L + i0) * 64);
        for (int idx = t; idx < 1024; idx += 128) {
            int r = idx >> 3, c = idx & 7;
            *(uint4*)(sm + (uint32_t)(r * 144 + c * 16)) = qh[idx];
        }
    }
    __syncthreads();
    uint32_t qf[2][4][4];
#pragma unroll
    for (int mg = 0; mg < 2; ++mg) {
        uint32_t base = sb + (uint32_t)((w * 32 + mg * 16) * STRD * 2) + offA;
#pragma unroll
        for (int kb = 0; kb < 4; ++kb) ldsm4(qf[mg][kb], base + kb * 32);
    }
    __syncthreads();

    load_kv(sb, b, jbase, t);
    CPA_COMMIT();

    float O[2][8][4];
#pragma unroll
    for (int mg = 0; mg < 2; ++mg)
#pragma unroll
        for (int n = 0; n < 8; ++n)
#pragma unroll
            for (int q = 0; q < 4; ++q) O[mg][n][q] = 0.f;
    float dsum[2][2] = {{0.f, 0.f}, {0.f, 0.f}};

#pragma unroll 1
    for (int tile = 0; tile < NTILE; ++tile) {
        int cur = tile & 1;
        if (tile < NTILE - 1) {
            load_kv(sb + (uint32_t)(cur ^ 1) * STAGEB, b, jbase + (tile + 1) * NJ, t);
            CPA_COMMIT();
            CPA_WAIT1();
        } else {
            CPA_WAIT0();
        }
        __syncthreads();

        const uint32_t stg = sb + (uint32_t)cur * STAGEB;

#pragma unroll
        for (int jh = 0; jh < 2; ++jh) {
            const uint32_t bBK = stg + KHO + offBK + (uint32_t)(jh * 64 * 144);
            const uint32_t bBV = stg + VHO + offBV + (uint32_t)(jh * 128);

            float S[2][8][4];
#pragma unroll
            for (int mg = 0; mg < 2; ++mg)
#pragma unroll
                for (int n = 0; n < 8; ++n)
#pragma unroll
                    for (int q = 0; q < 4; ++q) S[mg][n][q] = 0.f;

#pragma unroll
            for (int kb = 0; kb < 4; ++kb) {
#pragma unroll
                for (int np = 0; np < 4; ++np) {
                    uint32_t bh[4];
                    ldsm4(bh, bBK + (uint32_t)(np * 16 * STRD * 2) + kb * 32);
                    mma_bf16(S[0][np * 2],     qf[0][kb], bh[0], bh[1]);
                    mma_bf16(S[0][np * 2 + 1], qf[0][kb], bh[2], bh[3]);
                    mma_bf16(S[1][np * 2],     qf[1][kb], bh[0], bh[1]);
                    mma_bf16(S[1][np * 2 + 1], qf[1][kb], bh[2], bh[3]);
                }
            }

            uint32_t phi[2][4][4];
#pragma unroll
            for (int mg = 0; mg < 2; ++mg) {
                float rl = 0.f, rh = 0.f;
#pragma unroll
                for (int n = 0; n < 8; ++n) {
#pragma unroll
                    for (int q = 0; q < 4; ++q) S[mg][n][q] = ex2f(S[mg][n][q]);
                    rl += S[mg][n][0] + S[mg][n][1];
                    rh += S[mg][n][2] + S[mg][n][3];
                }
                dsum[mg][0] += rl; dsum[mg][1] += rh;
#pragma unroll
                for (int jb = 0; jb < 4; ++jb) {
#pragma unroll
                    for (int rp = 0; rp < 4; ++rp) {
                        int n = jb * 2 + (rp >> 1);
                        __half2 h2 = __floats2half2_rn(S[mg][n][(rp & 1) * 2 + 0],
                                                       S[mg][n][(rp & 1) * 2 + 1]);
                        phi[mg][jb][rp] = *(uint32_t*)&h2;
                    }
                }
            }

#pragma unroll
            for (int jb = 0; jb < 4; ++jb) {
#pragma unroll
                for (int vp = 0; vp < 4; ++vp) {
                    uint32_t bh[4];
                    ldsm4(bh, bBV + (uint32_t)(vp * 16 * VSTR * 2) + jb * 32);
                    mma_fp16(O[0][vp * 2],     phi[0][jb], bh[0], bh[1]);
                    mma_fp16(O[0][vp * 2 + 1], phi[0][jb], bh[2], bh[3]);
                    mma_fp16(O[1][vp * 2],     phi[1][jb], bh[0], bh[1]);
                    mma_fp16(O[1][vp * 2 + 1], phi[1][jb], bh[2], bh[3]);
                }
            }
        }
        __syncthreads();
    }

    // row-sum reduce across lanes; store partial denoms
#pragma unroll
    for (int mg = 0; mg < 2; ++mg) {
#pragma unroll
        for (int h = 0; h < 2; ++h) {
            float v = dsum[mg][h];
            v += __shfl_xor_sync(0xffffffffu, v, 1);
            v += __shfl_xor_sync(0xffffffffu, v, 2);
            if (tig == 0)
                g_pd[sp][(size_t)b * L + i0 + w * 32 + mg * 16 + gid + h * 8] = v;
        }
    }

    // ---- write partial O (un-normalized, fp16) in [v][i] layout via smem transpose
    __syncthreads();
    float* Os = (float*)sm;   // [64][132] floats = 33792B
#pragma unroll
    for (int mg = 0; mg < 2; ++mg) {
        int ir = w * 32 + mg * 16 + gid;
#pragma unroll
        for (int n = 0; n < 8; ++n) {
            int v0 = n * 8 + tig * 2;
            Os[v0 * 132 + ir]            = O[mg][n][0];
            Os[(v0 + 1) * 132 + ir]      = O[mg][n][1];
            Os[v0 * 132 + ir + 8]        = O[mg][n][2];
            Os[(v0 + 1) * 132 + ir + 8]  = O[mg][n][3];
        }
    }
    __syncthreads();
    {
        int v = t >> 1, hc = (t & 1) * 64;
        __half* dst = g_pO[sp] + ((size_t)b * 64 + v) * L + i0 + hc;
        const float* srcp = Os + v * 132 + hc;
#pragma unroll
        for (int c = 0; c < 16; ++c) {
            float4 f = *(const float4*)(srcp + c * 4);
            __half2 h0 = __floats2half2_rn(f.x, f.y);
            __half2 h1 = __floats2half2_rn(f.z, f.w);
            uint2 u;
            u.x = *(uint32_t*)&h0;
            u.y = *(uint32_t*)&h1;
            *(uint2*)(dst + c * 4) = u;
        }
    }
}

// ---------------- combine: out = sum(O_s) / sum(d_s) ----------------
__global__ __launch_bounds__(256) void combine_kernel(float* __restrict__ out) {
    int e0 = (blockIdx.x * 256 + threadIdx.x) * 4;   // index into [b][v][i]
    int b = e0 >> 18;
    int i = e0 & (L - 1);
    float num[4] = {0.f, 0.f, 0.f, 0.f}, den[4] = {0.f, 0.f, 0.f, 0.f};
#pragma unroll
    for (int s = 0; s < SPLIT; ++s) {
        uint2 u = *(const uint2*)&g_pO[s][e0];
        __half2 h0 = *(__half2*)&u.x;
        __half2 h1 = *(__half2*)&u.y;
        float2 p0 = __half22float2(h0);
        float2 p1 = __half22float2(h1);
        float4 d = *(const float4*)&g_pd[s][(size_t)b * L + i];
        num[0] += p0.x; num[1] += p0.y; num[2] += p1.x; num[3] += p1.y;
        den[0] += d.x;  den[1] += d.y;  den[2] += d.z;  den[3] += d.w;
    }
    float4 o;
    o.x = num[0] / den[0]; o.y = num[1] / den[1];
    o.z = num[2] / den[2]; o.w = num[3] / den[3];
    *(float4*)&out[e0] = o;
}

// ---------------- launch ----------------
extern "C" void kernel_launch(void* const* d_in, const int* in_sizes, int n_in,
                              void* d_out, int out_size) {
    const float* x     = (const float*)d_in[0];
    const float* x_enc = (const float*)d_in[1];
    const float* Wq    = (const float*)d_in[2];
    const float* bq    = (const float*)d_in[3];
    const float* Wk    = (const float*)d_in[4];
    const float* bk    = (const float*)d_in[5];
    const float* Wv    = (const float*)d_in[6];
    const float* bv    = (const float*)d_in[7];
    float* out = (float*)d_out;

    proj_kernel<<<dim3(L / 64, B, 3), 128, 20480>>>(x, x_enc, Wq, Wk, Wv, bq, bk, bv);

    static bool attr_set = false;
    if (!attr_set) {
        cudaFuncSetAttribute(attn_kernel, cudaFuncAttributeMaxDynamicSharedMemorySize,
                             2 * STAGEB);
        attr_set = true;
    }
    attn_kernel<<<dim3(L / MQ, B, SPLIT), 128, 2 * STAGEB>>>();

    combine_kernel<<<(B * 64 * L) / (256 * 4), 256>>>(out);
}

// round 15
// speedup vs baseline: 1.1949x; 1.0396x over previous
#include <cuda_runtime.h>
#include <cuda_bf16.h>
#include <cuda_fp16.h>
#include <math.h>
#include <stdint.h>

#define B    2
#define CIN  320
#define CENC 326
#define L    4096

#define CENC_P 352   // padded to multiple of 32
#define CIN_P  320

#define STRD 72      // bf16 row stride, K/Q attention tiles (144B)
#define VSTR 136     // fp16 row stride, V attention tiles (272B; 128-j rows)
#define WST2 40      // bf16 row stride in proj smem tiles (80B rows, 32-c chunks)

#define SPLIT 4
#define JSPAN (L / SPLIT)    // 1024
#define NJ    128
#define NTILE (JSPAN / NJ)   // 8
#define MQ    128            // queries per CTA (32 rows per warp, 2 m-groups)

#define LOG2E 1.4426950408889634f

// ---------------- scratch (device globals) ----------------
__device__ __nv_bfloat16 g_Qhi[B * L * 64];          // pre-scaled by log2e
__device__ __nv_bfloat16 g_Khi[B * L * 64];
__device__ __half        g_Vt[B * 64 * L];           // [b][v][l] fp16
__device__ __half g_pO[SPLIT][B * 64 * L];   // partial O (fp16), [sp][b][v][i]
__device__ float  g_pd[SPLIT][B * L];        // partial denominators

// ---------------- helpers ----------------
__device__ __forceinline__ uint32_t smem_u32(const void* p) {
    uint32_t a;
    asm("{ .reg .u64 t; cvta.to.shared.u64 t, %1; cvt.u32.u64 %0, t; }" : "=r"(a) : "l"(p));
    return a;
}
__device__ __forceinline__ void ldsm4(uint32_t r[4], uint32_t addr) {
    asm volatile("ldmatrix.sync.aligned.m8n8.x4.shared.b16 {%0,%1,%2,%3}, [%4];"
        : "=r"(r[0]), "=r"(r[1]), "=r"(r[2]), "=r"(r[3]) : "r"(addr));
}
__device__ __forceinline__ void mma_bf16(float c[4], const uint32_t a[4],
                                         uint32_t b0, uint32_t b1) {
    asm volatile("mma.sync.aligned.m16n8k16.row.col.f32.bf16.bf16.f32 "
        "{%0,%1,%2,%3}, {%4,%5,%6,%7}, {%8,%9}, {%0,%1,%2,%3};"
        : "+f"(c[0]), "+f"(c[1]), "+f"(c[2]), "+f"(c[3])
        : "r"(a[0]), "r"(a[1]), "r"(a[2]), "r"(a[3]), "r"(b0), "r"(b1));
}
__device__ __forceinline__ void mma_fp16(float c[4], const uint32_t a[4],
                                         uint32_t b0, uint32_t b1) {
    asm volatile("mma.sync.aligned.m16n8k16.row.col.f32.f16.f16.f32 "
        "{%0,%1,%2,%3}, {%4,%5,%6,%7}, {%8,%9}, {%0,%1,%2,%3};"
        : "+f"(c[0]), "+f"(c[1]), "+f"(c[2]), "+f"(c[3])
        : "r"(a[0]), "r"(a[1]), "r"(a[2]), "r"(a[3]), "r"(b0), "r"(b1));
}
__device__ __forceinline__ uint32_t exp2_f16x2(float e0, float e1) {
    uint32_t hs, pe;
    asm("cvt.rn.f16x2.f32 %0, %1, %2;" : "=r"(hs) : "f"(e1), "f"(e0));
    asm("ex2.approx.f16x2 %0, %1;" : "=r"(pe) : "r"(hs));
    return pe;
}
__device__ __forceinline__ void cpa16(uint32_t dst, const void* src) {
    asm volatile("cp.async.cg.shared.global [%0], [%1], 16;" :: "r"(dst), "l"(src));
}
#define CPA_COMMIT() asm volatile("cp.async.commit_group;" ::: "memory")
#define CPA_WAIT1()  asm volatile("cp.async.wait_group 1;" ::: "memory")
#define CPA_WAIT0()  asm volatile("cp.async.wait_group 0;" ::: "memory")

// ---------------- tensor-core projections (KC=32 chunks, inline W hi/lo split) ----
// smem bf16 tiles [64][WST2]=5120B: Xh@0, Xl@5120, Whs@10240, Wls@15360
__global__ __launch_bounds__(128) void proj_kernel(const float* __restrict__ x,
                                                   const float* __restrict__ x_enc,
                                                   const float* __restrict__ Wq,
                                                   const float* __restrict__ Wk,
                                                   const float* __restrict__ Wv,
                                                   const float* __restrict__ bq,
                                                   const float* __restrict__ bk,
                                                   const float* __restrict__ bv) {
    int z = blockIdx.z, b = blockIdx.y, l0 = blockIdx.x * 64;
    const float* src  = (z == 2) ? x : x_enc;
    const float* Wsrc = (z == 0) ? Wq : (z == 1) ? Wk : Wv;
    const float* bias = (z == 0) ? bq : (z == 1) ? bk : bv;
    int Cdim = (z == 2) ? CIN : CENC;
    int Cpad = (z == 2) ? CIN_P : CENC_P;

    extern __shared__ char psm[];
    __nv_bfloat16* Xh  = (__nv_bfloat16*)(psm);
    __nv_bfloat16* Xl  = (__nv_bfloat16*)(psm + 5120);
    __nv_bfloat16* Whs = (__nv_bfloat16*)(psm + 10240);
    __nv_bfloat16* Wls = (__nv_bfloat16*)(psm + 15360);
    __shared__ float nrmA[64];
    uint32_t sb = smem_u32(psm);

    int t = threadIdx.x, lane = t & 31, w = t >> 5;
    int gid = lane >> 2, tig = lane & 3, lr = lane & 7, lg = lane >> 3;

    float S[8][4];
#pragma unroll
    for (int n = 0; n < 8; ++n)
#pragma unroll
        for (int q = 0; q < 4; ++q) S[n][q] = 0.f;

    const float* srcb = src + (size_t)b * Cdim * L + l0;
    const uint32_t offB = (uint32_t)(((lr + (lg >> 1) * 8) * WST2 + (lg & 1) * 8) * 2);
    const uint32_t bX = sb + offB;

    int nCh = Cpad / 32;

    float xv[16];
#pragma unroll
    for (int i = 0; i < 16; ++i) {
        int idx = t + i * 128;
        int c = idx >> 6, l = idx & 63;
        xv[i] = (c < Cdim) ? __ldg(srcb + (size_t)c * L + l) : 0.f;
    }

    for (int ch = 0; ch < nCh; ++ch) {
        int c0 = ch * 32;
        __syncthreads();
#pragma unroll
        for (int i = 0; i < 16; ++i) {
            int idx = t + i * 128;
            int c = idx >> 6, l = idx & 63;
            __nv_bfloat16 h = __float2bfloat16(xv[i]);
            Xh[l * WST2 + c] = h;
            Xl[l * WST2 + c] = __float2bfloat16(xv[i] - __bfloat162float(h));
        }
#pragma unroll
        for (int i = 0; i < 8; ++i) {
            int idx = t + i * 128;
            int d = idx >> 4, cp = idx & 15;
            int c = c0 + cp * 2;
            float f0 = (c < Cdim)     ? __ldg(Wsrc + d * Cdim + c)     : 0.f;
            float f1 = (c + 1 < Cdim) ? __ldg(Wsrc + d * Cdim + c + 1) : 0.f;
            __nv_bfloat16 h0 = __float2bfloat16(f0);
            __nv_bfloat16 h1 = __float2bfloat16(f1);
            Whs[d * WST2 + cp * 2]     = h0;
            Whs[d * WST2 + cp * 2 + 1] = h1;
            Wls[d * WST2 + cp * 2]     = __float2bfloat16(f0 - __bfloat162float(h0));
            Wls[d * WST2 + cp * 2 + 1] = __float2bfloat16(f1 - __bfloat162float(h1));
        }
        __syncthreads();

        if (ch + 1 < nCh) {
            int c1 = (ch + 1) * 32;
#pragma unroll
            for (int i = 0; i < 16; ++i) {
                int idx = t + i * 128;
                int c = c1 + (idx >> 6), l = idx & 63;
                xv[i] = (c < Cdim) ? __ldg(srcb + (size_t)c * L + l) : 0.f;
            }
        }

#pragma unroll
        for (int kb = 0; kb < 2; ++kb) {
            uint32_t ah[4], al[4];
            {
                int r0 = (w * 16 + gid) * WST2 + kb * 16;
                int r8 = (w * 16 + gid + 8) * WST2 + kb * 16;
                ah[0] = *(const uint32_t*)&Whs[r0 + tig * 2];
                ah[1] = *(const uint32_t*)&Whs[r8 + tig * 2];
                ah[2] = *(const uint32_t*)&Whs[r0 + tig * 2 + 8];
                ah[3] = *(const uint32_t*)&Whs[r8 + tig * 2 + 8];
                al[0] = *(const uint32_t*)&Wls[r0 + tig * 2];
                al[1] = *(const uint32_t*)&Wls[r8 + tig * 2];
                al[2] = *(const uint32_t*)&Wls[r0 + tig * 2 + 8];
                al[3] = *(const uint32_t*)&Wls[r8 + tig * 2 + 8];
            }
#pragma unroll
            for (int np = 0; np < 4; ++np) {
                uint32_t bh[4], bl[4];
                ldsm4(bh, bX + (uint32_t)(np * 16 * WST2 * 2 + kb * 32));
                mma_bf16(S[np * 2],     ah, bh[0], bh[1]);
                mma_bf16(S[np * 2 + 1], ah, bh[2], bh[3]);
                mma_bf16(S[np * 2],     al, bh[0], bh[1]);
                mma_bf16(S[np * 2 + 1], al, bh[2], bh[3]);
                ldsm4(bl, bX + (uint32_t)(5120 + np * 16 * WST2 * 2 + kb * 32));
                mma_bf16(S[np * 2],     ah, bl[0], bl[1]);
                mma_bf16(S[np * 2 + 1], ah, bl[2], bl[3]);
            }
        }
    }

    float b0v = __ldg(bias + w * 16 + gid);
    float b8v = __ldg(bias + w * 16 + gid + 8);

    float* Osm = (float*)psm;   // [64][68] floats = 17408B (fits in 20480)
    __syncthreads();

    if (z < 2) {
#pragma unroll
        for (int n = 0; n < 8; ++n) {
            int lc = n * 8 + tig * 2, d0 = w * 16 + gid;
            Osm[lc * 68 + d0]           = S[n][0] + b0v;
            Osm[(lc + 1) * 68 + d0]     = S[n][1] + b0v;
            Osm[lc * 68 + d0 + 8]       = S[n][2] + b8v;
            Osm[(lc + 1) * 68 + d0 + 8] = S[n][3] + b8v;
        }
        __syncthreads();
        if (t < 64) {
            float ss = 0.f;
#pragma unroll
            for (int d = 0; d < 64; ++d) { float v = Osm[t * 68 + d]; ss += v * v; }
            nrmA[t] = 1.f / fmaxf(sqrtf(ss), 1e-6f);
        }
        __syncthreads();
        __nv_bfloat16* dh = (z == 0) ? g_Qhi : g_Khi;
        int l = t & 63, dg = t >> 6;
        float sc = nrmA[l];
        if (z == 0) sc *= LOG2E;                 // fold log2e into Q -> ex2 in attn
        size_t obase = ((size_t)b * L + l0 + l) * 64 + dg * 32;
#pragma unroll
        for (int i = 0; i < 8; ++i) {
            __nv_bfloat16 th[4];
#pragma unroll
            for (int k = 0; k < 4; ++k)
                th[k] = __float2bfloat16(Osm[l * 68 + dg * 32 + i * 4 + k] * sc);
            *(uint2*)&dh[obase + i * 4] = *(uint2*)th;
        }
    } else {
#pragma unroll
        for (int n = 0; n < 8; ++n) {
            int lc = n * 8 + tig * 2, d0 = w * 16 + gid;
            Osm[d0 * 68 + lc]           = S[n][0] + b0v;
            Osm[d0 * 68 + lc + 1]       = S[n][1] + b0v;
            Osm[(d0 + 8) * 68 + lc]     = S[n][2] + b8v;
            Osm[(d0 + 8) * 68 + lc + 1] = S[n][3] + b8v;
        }
        __syncthreads();
        int v = t >> 1, half = t & 1;
        size_t obase = ((size_t)b * 64 + v) * L + l0 + half * 32;
#pragma unroll
        for (int i = 0; i < 8; ++i) {
            __half th[4];
#pragma unroll
            for (int k = 0; k < 4; ++k)
                th[k] = __float2half(Osm[v * 68 + half * 32 + i * 4 + k]);
            *(uint2*)&g_Vt[obase + i * 4] = *(uint2*)th;
        }
    }
}

// ---------------- mma.sync flash attention (MQ=128, NJ=128, SPLIT=4, f16x2 exp) ---
#define KHO  0u
#define VHO  18432u
#define STAGEB 35840u

__device__ __forceinline__ void load_kv(uint32_t sbase, int b, int j0, int t) {
#pragma unroll
    for (int i = 0; i < 8; ++i) {
        int idx = t + i * 128;
        int r = idx >> 3, c = idx & 7;
        cpa16(sbase + KHO + (uint32_t)(r * 144 + c * 16),
              g_Khi + ((size_t)b * L + j0 + r) * 64 + c * 8);
    }
#pragma unroll
    for (int i = 0; i < 8; ++i) {
        int idx = t + i * 128;
        int v = idx >> 4, c16 = idx & 15;
        cpa16(sbase + VHO + (uint32_t)(v * 272 + c16 * 16),
              g_Vt + ((size_t)b * 64 + v) * L + j0 + c16 * 8);
    }
}

__global__ __launch_bounds__(128, 3) void attn_kernel() {
    extern __shared__ char sm[];
    const uint32_t sb = smem_u32(sm);
    const int t = threadIdx.x, lane = t & 31, w = t >> 5;
    const int b = blockIdx.y, i0 = blockIdx.x * MQ, sp = blockIdx.z;
    const int jbase = sp * JSPAN;
    const int gid = lane >> 2, tig = lane & 3;
    const int lr = lane & 7, lg = lane >> 3;

    const uint32_t offA  = (uint32_t)(((lr + ((lg & 1) << 3)) * STRD + ((lg >> 1) << 3)) * 2);
    const uint32_t offBK = (uint32_t)(((lr + ((lg >> 1) << 3)) * STRD + ((lg & 1) << 3)) * 2);
    const uint32_t offBV = (uint32_t)(((lr + ((lg >> 1) << 3)) * VSTR + ((lg & 1) << 3)) * 2);

    // ---- issue tile-0 load into buffer 1 FIRST (overlaps with Q staging below)
    load_kv(sb + STAGEB, b, jbase, t);
    CPA_COMMIT();

    // ---- stage Q (128 rows) into buffer-0 K area, build persistent A fragments
    {
        const uint4* qh = (const uint4*)(g_Qhi + ((size_t)b * L + i0) * 64);
        for (int idx = t; idx < 1024; idx += 128) {
            int r = idx >> 3, c = idx & 7;
            *(uint4*)(sm + (uint32_t)(r * 144 + c * 16)) = qh[idx];
        }
    }
    __syncthreads();
    uint32_t qf[2][4][4];
#pragma unroll
    for (int mg = 0; mg < 2; ++mg) {
        uint32_t base = sb + (uint32_t)((w * 32 + mg * 16) * STRD * 2) + offA;
#pragma unroll
        for (int kb = 0; kb < 4; ++kb) ldsm4(qf[mg][kb], base + kb * 32);
    }
    __syncthreads();

    float O[2][8][4];
#pragma unroll
    for (int mg = 0; mg < 2; ++mg)
#pragma unroll
        for (int n = 0; n < 8; ++n)
#pragma unroll
            for (int q = 0; q < 4; ++q) O[mg][n][q] = 0.f;
    float dsum[2][2] = {{0.f, 0.f}, {0.f, 0.f}};

#pragma unroll 1
    for (int tile = 0; tile < NTILE; ++tile) {
        int db = (tile & 1) ^ 1;         // data buffer for this tile
        if (tile < NTILE - 1) {
            load_kv(sb + (uint32_t)(db ^ 1) * STAGEB, b, jbase + (tile + 1) * NJ, t);
            CPA_COMMIT();
            CPA_WAIT1();
        } else {
            CPA_WAIT0();
        }
        __syncthreads();

        const uint32_t stg = sb + (uint32_t)db * STAGEB;

#pragma unroll
        for (int jh = 0; jh < 2; ++jh) {
            const uint32_t bBK = stg + KHO + offBK + (uint32_t)(jh * 64 * 144);
            const uint32_t bBV = stg + VHO + offBV + (uint32_t)(jh * 128);

            float S[2][8][4];
#pragma unroll
            for (int mg = 0; mg < 2; ++mg)
#pragma unroll
                for (int n = 0; n < 8; ++n)
#pragma unroll
                    for (int q = 0; q < 4; ++q) S[mg][n][q] = 0.f;

#pragma unroll
            for (int kb = 0; kb < 4; ++kb) {
#pragma unroll
                for (int np = 0; np < 4; ++np) {
                    uint32_t bh[4];
                    ldsm4(bh, bBK + (uint32_t)(np * 16 * STRD * 2) + kb * 32);
                    mma_bf16(S[0][np * 2],     qf[0][kb], bh[0], bh[1]);
                    mma_bf16(S[0][np * 2 + 1], qf[0][kb], bh[2], bh[3]);
                    mma_bf16(S[1][np * 2],     qf[1][kb], bh[0], bh[1]);
                    mma_bf16(S[1][np * 2 + 1], qf[1][kb], bh[2], bh[3]);
                }
            }

            // ---- exp2 in f16x2 (one MUFU per 2 scores); result IS the P fragment
            uint32_t phi[2][4][4];
#pragma unroll
            for (int mg = 0; mg < 2; ++mg) {
                __half2 a0 = __float2half2_rn(0.f);
                __half2 a1 = __float2half2_rn(0.f);
#pragma unroll
                for (int jb = 0; jb < 4; ++jb) {
#pragma unroll
                    for (int rp = 0; rp < 4; ++rp) {
                        int n = jb * 2 + (rp >> 1);
                        uint32_t pe = exp2_f16x2(S[mg][n][(rp & 1) * 2 + 0],
                                                 S[mg][n][(rp & 1) * 2 + 1]);
                        phi[mg][jb][rp] = pe;
                        if (rp & 1) a1 = __hadd2(a1, *(__half2*)&pe);
                        else        a0 = __hadd2(a0, *(__half2*)&pe);
                    }
                }
                float2 f0 = __half22float2(a0);
                float2 f1 = __half22float2(a1);
                dsum[mg][0] += f0.x + f0.y;
                dsum[mg][1] += f1.x + f1.y;
            }

#pragma unroll
            for (int jb = 0; jb < 4; ++jb) {
#pragma unroll
                for (int vp = 0; vp < 4; ++vp) {
                    uint32_t bh[4];
                    ldsm4(bh, bBV + (uint32_t)(vp * 16 * VSTR * 2) + jb * 32);
                    mma_fp16(O[0][vp * 2],     phi[0][jb], bh[0], bh[1]);
                    mma_fp16(O[0][vp * 2 + 1], phi[0][jb], bh[2], bh[3]);
                    mma_fp16(O[1][vp * 2],     phi[1][jb], bh[0], bh[1]);
                    mma_fp16(O[1][vp * 2 + 1], phi[1][jb], bh[2], bh[3]);
                }
            }
        }
        __syncthreads();
    }

    // row-sum reduce across lanes; store partial denoms
#pragma unroll
    for (int mg = 0; mg < 2; ++mg) {
#pragma unroll
        for (int h = 0; h < 2; ++h) {
            float v = dsum[mg][h];
            v += __shfl_xor_sync(0xffffffffu, v, 1);
            v += __shfl_xor_sync(0xffffffffu, v, 2);
            if (tig == 0)
                g_pd[sp][(size_t)b * L + i0 + w * 32 + mg * 16 + gid + h * 8] = v;
        }
    }

    // ---- write partial O (un-normalized, fp16) in [v][i] layout via smem transpose
    __syncthreads();
    float* Os = (float*)sm;   // [64][132] floats = 33792B
#pragma unroll
    for (int mg = 0; mg < 2; ++mg) {
        int ir = w * 32 + mg * 16 + gid;
#pragma unroll
        for (int n = 0; n < 8; ++n) {
            int v0 = n * 8 + tig * 2;
            Os[v0 * 132 + ir]            = O[mg][n][0];
            Os[(v0 + 1) * 132 + ir]      = O[mg][n][1];
            Os[v0 * 132 + ir + 8]        = O[mg][n][2];
            Os[(v0 + 1) * 132 + ir + 8]  = O[mg][n][3];
        }
    }
    __syncthreads();
    {
        int v = t >> 1, hc = (t & 1) * 64;
        __half* dst = g_pO[sp] + ((size_t)b * 64 + v) * L + i0 + hc;
        const float* srcp = Os + v * 132 + hc;
#pragma unroll
        for (int c = 0; c < 16; ++c) {
            float4 f = *(const float4*)(srcp + c * 4);
            __half2 h0 = __floats2half2_rn(f.x, f.y);
            __half2 h1 = __floats2half2_rn(f.z, f.w);
            uint2 u;
            u.x = *(uint32_t*)&h0;
            u.y = *(uint32_t*)&h1;
            *(uint2*)(dst + c * 4) = u;
        }
    }
}

// ---------------- combine: out = sum(O_s) / sum(d_s) ----------------
__global__ __launch_bounds__(256) void combine_kernel(float* __restrict__ out) {
    int e0 = (blockIdx.x * 256 + threadIdx.x) * 4;   // index into [b][v][i]
    int b = e0 >> 18;
    int i = e0 & (L - 1);
    float num[4] = {0.f, 0.f, 0.f, 0.f}, den[4] = {0.f, 0.f, 0.f, 0.f};
#pragma unroll
    for (int s = 0; s < SPLIT; ++s) {
        uint2 u = *(const uint2*)&g_pO[s][e0];
        __half2 h0 = *(__half2*)&u.x;
        __half2 h1 = *(__half2*)&u.y;
        float2 p0 = __half22float2(h0);
        float2 p1 = __half22float2(h1);
        float4 d = *(const float4*)&g_pd[s][(size_t)b * L + i];
        num[0] += p0.x; num[1] += p0.y; num[2] += p1.x; num[3] += p1.y;
        den[0] += d.x;  den[1] += d.y;  den[2] += d.z;  den[3] += d.w;
    }
    float4 o;
    o.x = num[0] / den[0]; o.y = num[1] / den[1];
    o.z = num[2] / den[2]; o.w = num[3] / den[3];
    *(float4*)&out[e0] = o;
}

// ---------------- launch ----------------
extern "C" void kernel_launch(void* const* d_in, const int* in_sizes, int n_in,
                              void* d_out, int out_size) {
    const float* x     = (const float*)d_in[0];
    const float* x_enc = (const float*)d_in[1];
    const float* Wq    = (const float*)d_in[2];
    const float* bq    = (const float*)d_in[3];
    const float* Wk    = (const float*)d_in[4];
    const float* bk    = (const float*)d_in[5];
    const float* Wv    = (const float*)d_in[6];
    const float* bv    = (const float*)d_in[7];
    float* out = (float*)d_out;

    proj_kernel<<<dim3(L / 64, B, 3), 128, 20480>>>(x, x_enc, Wq, Wk, Wv, bq, bk, bv);

    static bool attr_set = false;
    if (!attr_set) {
        cudaFuncSetAttribute(attn_kernel, cudaFuncAttributeMaxDynamicSharedMemorySize,
                             2 * STAGEB);
        attr_set = true;
    }
    attn_kernel<<<dim3(L / MQ, B, SPLIT), 128, 2 * STAGEB>>>();

    combine_kernel<<<(B * 64 * L) / (256 * 4), 256>>>(out);
}